// round 9
// baseline (speedup 1.0000x reference)
#include <cuda_runtime.h>
#include <cuda_bf16.h>

// LIFActivation, single fused kernel, per-block threshold search (warp 0),
// 256-bit (v8) global loads/stores, 8 independent streams per thread.
// No L2 policy hints, no occupancy cap (R8 showed both regress on sm_103a).
//
// out(x) is a 4-threshold step function of x: n_spikes(x) is monotone for
// fixed scale, thresholds lie within a few ulp of RN(k*s/4). Warp 0 searches
// a +/-16-ulp window with a 9-ary ballot search probing the EXACT reference
// fp32 sequence (bracket-verified, full-range fallback -> correctness
// unconditional). Exact-divisibility fast path drops bounds predicates.

__device__ __forceinline__ int nspikes_ref(float x, float s) {
    float c = __fdiv_rn(fmaxf(x, 0.0f), s);  // IEEE RN div, exact ref semantics
    float v = 0.0f;
    int n = 0;
#pragma unroll
    for (int t = 0; t < 4; ++t) {
        v += c;
        if (v >= 1.0f) {  // H(v-1)==1 <=> v>=1
            v -= 1.0f;
            n += 1;
        }
    }
    return n;
}

// Warp-collective (warp 0 only): lanes [8g,8g+8) find the smallest
// nonnegative float bits u with nspikes_ref(u,s) >= g+1.
__device__ __forceinline__ void search_thresholds(float s, int lane,
                                                  float* sX, float* sV) {
    const unsigned FULL = 0xFFFFFFFFu;
    const unsigned FMAX = 0x7F7FFFFFu;
    int grp = lane >> 3;
    int sub = lane & 7;

    int target = grp + 1;
    float qs = 0.25f * s;                  // exact (power-of-2 scale)
    unsigned cb = __float_as_uint((float)target * qs);

    const unsigned W = 16u;
    unsigned lo = (cb > W) ? cb - W : 0u;
    unsigned hi = (cb >= FMAX - W) ? FMAX : cb + W;

    bool lo_sat = nspikes_ref(__uint_as_float(lo), s) >= target;
    bool hi_sat = nspikes_ref(__uint_as_float(hi), s) >= target;
    bool feasible = true;
    if (lo_sat) {                 // threshold below window: bracket (0, lo]
        hi = lo; lo = 0u;
    } else if (!hi_sat) {         // threshold above window
        if (nspikes_ref(__uint_as_float(FMAX), s) >= target) {
            lo = hi; hi = FMAX;
        } else {
            feasible = false;
            lo = hi;
        }
    }

    for (int it = 0; it < 12; ++it) {
        bool conv = (hi - lo) <= 1u;
        if (__all_sync(FULL, conv)) break;
        unsigned long long range = (unsigned long long)(hi - lo);
        unsigned p = lo + (unsigned)(range * (unsigned long long)(sub + 1) / 9ull);
        bool sat = (!conv) && (nspikes_ref(__uint_as_float(p), s) >= target);
        unsigned bal = __ballot_sync(FULL, sat);
        if (!conv) {
            unsigned g = (bal >> (grp * 8)) & 0xFFu;
            if (g == 0u) {
                lo += (unsigned)(range * 8ull / 9ull);
            } else {
                int j = __ffs((int)g) - 1;
                hi = lo + (unsigned)(range * (unsigned long long)(j + 1) / 9ull);
                if (j > 0)
                    lo += (unsigned)(range * (unsigned long long)j / 9ull);
            }
        }
    }

    if (sub == 0) {
        sX[grp] = feasible ? __uint_as_float(hi) : __int_as_float(0x7F800000);
        sV[grp] = (float)target * qs;  // RN(k*RN(s/4)) == RN((k/4)*s)
    }
}

// 256-bit global load/store (Blackwell sm_100+), default cache policy.
__device__ __forceinline__ void ldg_v8(const float* __restrict__ p, float* r) {
    asm("ld.global.nc.v8.f32 {%0,%1,%2,%3,%4,%5,%6,%7}, [%8];"
        : "=f"(r[0]), "=f"(r[1]), "=f"(r[2]), "=f"(r[3]),
          "=f"(r[4]), "=f"(r[5]), "=f"(r[6]), "=f"(r[7])
        : "l"(p));
}
__device__ __forceinline__ void stg_v8(float* __restrict__ p, const float* r) {
    asm volatile("st.global.v8.f32 [%0], {%1,%2,%3,%4,%5,%6,%7,%8};"
        :: "l"(p),
           "f"(r[0]), "f"(r[1]), "f"(r[2]), "f"(r[3]),
           "f"(r[4]), "f"(r[5]), "f"(r[6]), "f"(r[7])
        : "memory");
}

__device__ __forceinline__ float lif_sel(float x, float4 X, float4 V) {
    float r = 0.0f;
    r = (x >= X.x) ? V.x : r;
    r = (x >= X.y) ? V.y : r;
    r = (x >= X.z) ? V.z : r;
    r = (x >= X.w) ? V.w : r;
    return r;   // NaN -> all false -> 0, matches reference
}

// S streams of v8 per thread; CHECKED=0 when grid tiles n8 exactly.
template <int S, int CHECKED>
__global__ void __launch_bounds__(256)
lif_fused_kernel(const float* __restrict__ x,
                 const float* __restrict__ scale_ptr,
                 float* __restrict__ out, int n8, int stride) {
    __shared__ float sX[4];
    __shared__ float sV[4];

    int tid = threadIdx.x;
    int i   = blockIdx.x * blockDim.x + tid;

    float a[S][8];
#pragma unroll
    for (int k = 0; k < S; ++k) {
        int idx = i + k * stride;
        if (!CHECKED || idx < n8) ldg_v8(x + (size_t)idx * 8, a[k]);
    }

    if (tid < 32) {
        float s = fmaxf(__ldg(scale_ptr), 1e-12f);
        search_thresholds(s, tid, sX, sV);
    }
    __syncthreads();

    float4 X = make_float4(sX[0], sX[1], sX[2], sX[3]);
    float4 V = make_float4(sV[0], sV[1], sV[2], sV[3]);

#pragma unroll
    for (int k = 0; k < S; ++k) {
        int idx = i + k * stride;
        if (!CHECKED || idx < n8) {
            float r[8];
#pragma unroll
            for (int e = 0; e < 8; ++e) r[e] = lif_sel(a[k][e], X, V);
            stg_v8(out + (size_t)idx * 8, r);
        }
    }
}

extern "C" void kernel_launch(void* const* d_in, const int* in_sizes, int n_in,
                              void* d_out, int out_size) {
    const float* x     = (const float*)d_in[0];
    const float* scale = (const float*)d_in[1];
    float* out = (float*)d_out;

    int n = out_size;        // 4096*8192 = 2^25
    const int threads = 256;

    if ((n & 31) == 0) {
        int n8 = n >> 3;
        // 8-stream exact path: n8 must split into 8 equal stride chunks,
        // each a multiple of blockDim.
        if ((n8 & 7) == 0 && ((n8 >> 3) % threads) == 0) {
            int stride = n8 >> 3;
            int blocks = stride / threads;   // 2048 for n=2^25
            lif_fused_kernel<8, 0><<<blocks, threads>>>(x, scale, out, n8, stride);
            return;
        }
        int stride = (n8 + 7) >> 3;
        int blocks = (stride + threads - 1) / threads;
        lif_fused_kernel<8, 1><<<blocks, threads>>>(x, scale, out, n8, stride);
        return;
    }
    // General fallback (n not 32-divisible): 4-stream checked v8 over the
    // 8-aligned region; shapes in this problem are always 2^25.
    int n8 = n >> 3;
    int stride = (n8 + 3) >> 2;
    int blocks = (stride + threads - 1) / threads;
    lif_fused_kernel<4, 1><<<blocks, threads>>>(x, scale, out, n8, stride);
}

// round 10
// speedup vs baseline: 1.2067x; 1.2067x over previous
#include <cuda_runtime.h>
#include <cuda_bf16.h>

// LIFActivation, single fused kernel — R7 configuration (best so far) with
// block size 128 for higher residency (regs ~56 packs ~9 blocks/SM).
//
// out(x) is a 4-threshold step function of x: n_spikes(x) is monotone for
// fixed scale, thresholds lie within a few ulp of RN(k*s/4). Warp 0 of each
// block searches a +/-16-ulp window with a 9-ary ballot search probing the
// EXACT reference fp32 sequence (bracket-verified, full-range fallback ->
// correctness unconditional). 4 independent v8 (256-bit) streams per thread.

__device__ __forceinline__ int nspikes_ref(float x, float s) {
    float c = __fdiv_rn(fmaxf(x, 0.0f), s);  // IEEE RN div, exact ref semantics
    float v = 0.0f;
    int n = 0;
#pragma unroll
    for (int t = 0; t < 4; ++t) {
        v += c;
        if (v >= 1.0f) {  // H(v-1)==1 <=> v>=1
            v -= 1.0f;
            n += 1;
        }
    }
    return n;
}

// Warp-collective (warp 0 only): lanes [8g,8g+8) find the smallest
// nonnegative float bits u with nspikes_ref(u,s) >= g+1.
__device__ __forceinline__ void search_thresholds(float s, int lane,
                                                  float* sX, float* sV) {
    const unsigned FULL = 0xFFFFFFFFu;
    const unsigned FMAX = 0x7F7FFFFFu;
    int grp = lane >> 3;
    int sub = lane & 7;

    int target = grp + 1;
    float qs = 0.25f * s;                  // exact (power-of-2 scale)
    unsigned cb = __float_as_uint((float)target * qs);

    const unsigned W = 16u;
    unsigned lo = (cb > W) ? cb - W : 0u;
    unsigned hi = (cb >= FMAX - W) ? FMAX : cb + W;

    bool lo_sat = nspikes_ref(__uint_as_float(lo), s) >= target;
    bool hi_sat = nspikes_ref(__uint_as_float(hi), s) >= target;
    bool feasible = true;
    if (lo_sat) {                 // threshold below window: bracket (0, lo]
        hi = lo; lo = 0u;
    } else if (!hi_sat) {         // threshold above window
        if (nspikes_ref(__uint_as_float(FMAX), s) >= target) {
            lo = hi; hi = FMAX;
        } else {
            feasible = false;
            lo = hi;
        }
    }

    for (int it = 0; it < 12; ++it) {
        bool conv = (hi - lo) <= 1u;
        if (__all_sync(FULL, conv)) break;
        unsigned long long range = (unsigned long long)(hi - lo);
        unsigned p = lo + (unsigned)(range * (unsigned long long)(sub + 1) / 9ull);
        bool sat = (!conv) && (nspikes_ref(__uint_as_float(p), s) >= target);
        unsigned bal = __ballot_sync(FULL, sat);
        if (!conv) {
            unsigned g = (bal >> (grp * 8)) & 0xFFu;
            if (g == 0u) {
                lo += (unsigned)(range * 8ull / 9ull);
            } else {
                int j = __ffs((int)g) - 1;
                hi = lo + (unsigned)(range * (unsigned long long)(j + 1) / 9ull);
                if (j > 0)
                    lo += (unsigned)(range * (unsigned long long)j / 9ull);
            }
        }
    }

    if (sub == 0) {
        sX[grp] = feasible ? __uint_as_float(hi) : __int_as_float(0x7F800000);
        sV[grp] = (float)target * qs;  // RN(k*RN(s/4)) == RN((k/4)*s)
    }
}

// 256-bit global load/store (Blackwell sm_100+), default cache policy.
__device__ __forceinline__ void ldg_v8(const float* __restrict__ p, float* r) {
    asm("ld.global.nc.v8.f32 {%0,%1,%2,%3,%4,%5,%6,%7}, [%8];"
        : "=f"(r[0]), "=f"(r[1]), "=f"(r[2]), "=f"(r[3]),
          "=f"(r[4]), "=f"(r[5]), "=f"(r[6]), "=f"(r[7])
        : "l"(p));
}
__device__ __forceinline__ void stg_v8(float* __restrict__ p, const float* r) {
    asm volatile("st.global.v8.f32 [%0], {%1,%2,%3,%4,%5,%6,%7,%8};"
        :: "l"(p),
           "f"(r[0]), "f"(r[1]), "f"(r[2]), "f"(r[3]),
           "f"(r[4]), "f"(r[5]), "f"(r[6]), "f"(r[7])
        : "memory");
}

__device__ __forceinline__ float lif_sel(float x, float4 X, float4 V) {
    float r = 0.0f;
    r = (x >= X.x) ? V.x : r;
    r = (x >= X.y) ? V.y : r;
    r = (x >= X.z) ? V.z : r;
    r = (x >= X.w) ? V.w : r;
    return r;   // NaN -> all false -> 0, matches reference
}

// 4 independent 32-byte streams per thread, front-batched before the barrier.
__global__ void __launch_bounds__(128)
lif_fused_kernel(const float* __restrict__ x,
                 const float* __restrict__ scale_ptr,
                 float* __restrict__ out, int n8, int quarter) {
    __shared__ float sX[4];
    __shared__ float sV[4];

    int tid = threadIdx.x;
    int i   = blockIdx.x * blockDim.x + tid;

    int  idx[4];
    bool ok[4];
    float a[4][8];
#pragma unroll
    for (int k = 0; k < 4; ++k) {
        idx[k] = i + k * quarter;
        ok[k]  = idx[k] < n8;
    }
#pragma unroll
    for (int k = 0; k < 4; ++k)
        if (ok[k]) ldg_v8(x + (size_t)idx[k] * 8, a[k]);

    if (tid < 32) {
        float s = fmaxf(__ldg(scale_ptr), 1e-12f);
        search_thresholds(s, tid, sX, sV);
    }
    __syncthreads();

    float4 X = make_float4(sX[0], sX[1], sX[2], sX[3]);
    float4 V = make_float4(sV[0], sV[1], sV[2], sV[3]);

#pragma unroll
    for (int k = 0; k < 4; ++k) {
        if (ok[k]) {
            float r[8];
#pragma unroll
            for (int e = 0; e < 8; ++e) r[e] = lif_sel(a[k][e], X, V);
            stg_v8(out + (size_t)idx[k] * 8, r);
        }
    }
}

extern "C" void kernel_launch(void* const* d_in, const int* in_sizes, int n_in,
                              void* d_out, int out_size) {
    const float* x     = (const float*)d_in[0];
    const float* scale = (const float*)d_in[1];
    float* out = (float*)d_out;

    int n  = out_size;       // 4096*8192 = 2^25 (divisible by 32)
    int n8 = n >> 3;         // v8 (32-byte) chunk count
    int quarter = (n8 + 3) >> 2;

    const int threads = 128;
    int blocks = (quarter + threads - 1) / threads;
    lif_fused_kernel<<<blocks, threads>>>(x, scale, out, n8, quarter);
}